// round 7
// baseline (speedup 1.0000x reference)
#include <cuda_runtime.h>
#include <cstdint>
#include <math.h>

#define HIDDEN  4096
#define NEXP    128
#define TOPK    8
#define BM      64
#define BK      32
#define BKP     36      // As row stride (floats): 144B, 16B-aligned float4 reads
#define BNP     132     // Bs row pad: 528B stride, keeps LDS.128 aligned
#define THREADS 256
#define NSTAGE  (HIDDEN / BK)

#define AS_STAGE (BM * BKP)       // 2304 floats
#define BS_STAGE (BK * BNP)       // 4224 floats
#define SMEM_FLOATS (2*AS_STAGE + 2*BS_STAGE + NEXP)   // 13184 -> 52736 B
#define AS(buf,m,k)  sm_As[(buf)*AS_STAGE + (m)*BKP + (k)]
#define BS(buf,k,e)  sm_Bs[(buf)*BS_STAGE + (k)*BNP + (e)]

typedef unsigned long long u64;

// k-major transposed router weight: Wt[k][e]
__device__ float g_Wt[HIDDEN * NEXP];

__device__ __forceinline__ u64 pk2(float lo, float hi) {
    u64 r; asm("mov.b64 %0, {%1, %2};" : "=l"(r) : "f"(lo), "f"(hi)); return r;
}
__device__ __forceinline__ void upk2(u64 v, float& lo, float& hi) {
    asm("mov.b64 {%0, %1}, %2;" : "=f"(lo), "=f"(hi) : "l"(v));
}
// Packed dual FMA: d.lo += a.lo*b.lo ; d.hi += a.hi*b.hi  (FFMA2, PTX-only)
__device__ __forceinline__ void fma2(u64& d, u64 a, u64 b) {
    asm("fma.rn.f32x2 %0, %1, %2, %0;" : "+l"(d) : "l"(a), "l"(b));
}
__device__ __forceinline__ void cp16(uint32_t dst, const void* src) {
    asm volatile("cp.async.cg.shared.global [%0], [%1], 16;\n" :: "r"(dst), "l"(src));
}
#define CP_COMMIT() asm volatile("cp.async.commit_group;\n" ::: "memory")
#define CP_WAIT0()  asm volatile("cp.async.wait_group 0;\n"  ::: "memory")

// ---- W transpose: g_Wt[k][e] = W[e][k]  (once per launch, ~3us) ----
__global__ void transpose_w_kernel(const float* __restrict__ W) {
    __shared__ float t[32][33];
    const int k0 = blockIdx.x * 32, e0 = blockIdx.y * 32;
    const int x = threadIdx.x & 31, y = threadIdx.x >> 5;
    #pragma unroll
    for (int j = 0; j < 4; j++) {
        const int e = y + j * 8;
        t[e][x] = W[(size_t)(e0 + e) * HIDDEN + k0 + x];
    }
    __syncthreads();
    #pragma unroll
    for (int j = 0; j < 4; j++) {
        const int k = y + j * 8;
        g_Wt[(size_t)(k0 + k) * NEXP + e0 + x] = t[x][k];
    }
}

// One CTA: 64 tokens x 128 experts, 256 threads (8 warps -> 2 warps/SMSP).
// Thread (tx=tid&15, ty=tid>>4): tokens [ty*4, ty*4+4) x experts [tx*8, tx*8+8).
// Half-warp (width 16, fixed ty) holds 4 full token rows -> register top-k.
__global__ __launch_bounds__(THREADS, 2)
void router_topk_kernel(const float* __restrict__ h,
                        const float* __restrict__ bias,
                        float* __restrict__ outI,
                        float* __restrict__ outW)
{
    extern __shared__ float smem[];
    float* sm_As   = smem;                      // [2][BM][BKP]
    float* sm_Bs   = smem + 2 * AS_STAGE;       // [2][BK][BNP]
    float* bias_s  = sm_Bs + 2 * BS_STAGE;      // [NEXP]

    const int tid = threadIdx.x;
    const int tx  = tid & 15;
    const int ty  = tid >> 4;
    const int m0  = blockIdx.x * BM;

    if (tid < NEXP) bias_s[tid] = bias[tid];

    u64 acc[4][4];
    #pragma unroll
    for (int i = 0; i < 4; i++)
        #pragma unroll
        for (int p = 0; p < 4; p++) acc[i][p] = pk2(0.f, 0.f);

    // A: 512 float4-chunks/stage, 2 per thread. m=c>>3, kq=c&7.
    int aM[2], aKq[2];
    #pragma unroll
    for (int j = 0; j < 2; j++) { int c = tid + THREADS * j; aM[j] = c >> 3; aKq[j] = c & 7; }
    // B cp.async: 1024 chunks/stage, 4 per thread. k=c>>5, e4=c&31.
    int bK[4], bE4[4];
    #pragma unroll
    for (int j = 0; j < 4; j++) { int c = tid + THREADS * j; bK[j] = c >> 5; bE4[j] = c & 31; }

    const uint32_t smemBsBase = (uint32_t)__cvta_generic_to_shared(sm_Bs);

    float4 aReg[2];

    // ---- Prologue: stage 0 ----
    #pragma unroll
    for (int j = 0; j < 4; j++) {
        uint32_t dst = smemBsBase + (uint32_t)((bK[j] * BNP + bE4[j] * 4) * 4);
        cp16(dst, g_Wt + (size_t)bK[j] * NEXP + bE4[j] * 4);
    }
    CP_COMMIT();
    #pragma unroll
    for (int j = 0; j < 2; j++)
        aReg[j] = *(const float4*)(h + (size_t)(m0 + aM[j]) * HIDDEN + aKq[j] * 4);

    for (int s = 0; s < NSTAGE; s++) {
        const int buf = s & 1;

        CP_WAIT0();                     // B(s) landed
        #pragma unroll
        for (int j = 0; j < 2; j++)     // A(s): STS.128, row-major (no transpose)
            *(float4*)&AS(buf, aM[j], aKq[j] * 4) = aReg[j];
        __syncthreads();

        // Prefetch stage s+1 (overlaps with FMA loop below)
        if (s + 1 < NSTAGE) {
            const int k0n = (s + 1) * BK;
            const int nb  = buf ^ 1;
            #pragma unroll
            for (int j = 0; j < 4; j++) {
                uint32_t dst = smemBsBase +
                    (uint32_t)((nb * BS_STAGE + bK[j] * BNP + bE4[j] * 4) * 4);
                cp16(dst, g_Wt + (size_t)(k0n + bK[j]) * NEXP + bE4[j] * 4);
            }
            #pragma unroll
            for (int j = 0; j < 2; j++)
                aReg[j] = *(const float4*)(h + (size_t)(m0 + aM[j]) * HIDDEN + k0n + aKq[j] * 4);
        }
        CP_COMMIT();                    // (empty group when s+1==NSTAGE)

        // Inner product: 4 k-steps per iteration; A frag via LDS.128
        #pragma unroll
        for (int kb = 0; kb < BK; kb += 4) {
            float4 af[4];
            #pragma unroll
            for (int i = 0; i < 4; i++)
                af[i] = *(const float4*)&AS(buf, ty * 4 + i, kb);
            #pragma unroll
            for (int kk = 0; kk < 4; kk++) {
                const ulonglong2 b0 = *(const ulonglong2*)&BS(buf, kb + kk, tx * 8);
                const ulonglong2 b1 = *(const ulonglong2*)&BS(buf, kb + kk, tx * 8 + 4);
                #pragma unroll
                for (int i = 0; i < 4; i++) {
                    const float av = ((const float*)&af[i])[kk];
                    const u64 aa = pk2(av, av);
                    fma2(acc[i][0], aa, b0.x);
                    fma2(acc[i][1], aa, b0.y);
                    fma2(acc[i][2], aa, b1.x);
                    fma2(acc[i][3], aa, b1.y);
                }
            }
        }
        __syncthreads();
    }

    // ---- Epilogue: sigmoid + bias, top-8 (tie -> lowest index), normalize ----
    const unsigned FULL = 0xffffffffu;
    #pragma unroll
    for (int i = 0; i < 4; i++) {
        float sc[8];
        #pragma unroll
        for (int p = 0; p < 4; p++) {
            float lo, hi; upk2(acc[i][p], lo, hi);
            sc[2 * p] = lo; sc[2 * p + 1] = hi;
        }
        #pragma unroll
        for (int j = 0; j < 8; j++) {
            float sig = 1.0f / (1.0f + expf(-sc[j]));
            sc[j] = sig + bias_s[tx * 8 + j];   // corrected score
        }

        float rem[8];
        #pragma unroll
        for (int j = 0; j < 8; j++) rem[j] = sc[j];

        int   topi[TOPK];
        float topraw[TOPK];
        float denom = 1e-20f;

        #pragma unroll
        for (int sel = 0; sel < TOPK; sel++) {
            float bv = -3.4e38f; int bi = NEXP;
            #pragma unroll
            for (int j = 0; j < 8; j++)
                if (rem[j] > bv) { bv = rem[j]; bi = tx * 8 + j; }
            #pragma unroll
            for (int off = 8; off; off >>= 1) {
                float ov = __shfl_xor_sync(FULL, bv, off, 16);
                int   oi = __shfl_xor_sync(FULL, bi, off, 16);
                if (ov > bv || (ov == bv && oi < bi)) { bv = ov; bi = oi; }
            }
            topi[sel]   = bi;
            float raw   = bv - bias_s[bi];      // raw sigmoid score
            topraw[sel] = raw;
            denom      += raw;
            const int lj = bi - tx * 8;
            if (lj >= 0 && lj < 8) rem[lj] = -3.4e38f;
        }

        if (tx == 0) {
            const size_t t = (size_t)(m0 + ty * 4 + i);
            const float inv = 1.0f / denom;
            #pragma unroll
            for (int sel = 0; sel < TOPK; sel++) {
                outI[t * TOPK + sel] = (float)topi[sel];
                outW[t * TOPK + sel] = topraw[sel] * inv;
            }
        }
    }
}

extern "C" void kernel_launch(void* const* d_in, const int* in_sizes, int n_in,
                              void* d_out, int out_size)
{
    const float* h    = (const float*)d_in[0];   // hidden_states [B,S,H] fp32
    const float* W    = (const float*)d_in[1];   // weight [E,H] fp32
    const float* bias = (const float*)d_in[2];   // e_score_correction_bias [E]

    const int T = in_sizes[0] / HIDDEN;          // 16384 tokens

    float* out  = (float*)d_out;
    float* outI = out;                           // indices as fp32
    float* outW = out + (size_t)T * TOPK;        // weights

    dim3 tgrid(HIDDEN / 32, NEXP / 32);
    transpose_w_kernel<<<tgrid, 256>>>(W);

    static int smem_set = 0;
    if (!smem_set) {
        cudaFuncSetAttribute(router_topk_kernel,
                             cudaFuncAttributeMaxDynamicSharedMemorySize,
                             SMEM_FLOATS * sizeof(float));
        smem_set = 1;
    }
    router_topk_kernel<<<T / BM, THREADS, SMEM_FLOATS * sizeof(float)>>>(h, bias, outI, outW);
}

// round 10
// speedup vs baseline: 1.2327x; 1.2327x over previous
#include <cuda_runtime.h>
#include <cuda_bf16.h>
#include <cstdint>
#include <math.h>

#define HIDDEN  4096
#define NEXP    128
#define TOPK    8
#define TM      128                  // tokens per CTA
#define KT      64                   // k per stage (64 bf16 = 128B rows)
#define STAGES  (HIDDEN / KT)        // 64
#define THREADS 256
#define TSTRIDE 144                  // tile row stride bytes (128B data + 16B pad)
#define TILE    (TM * TSTRIDE)       // 18432 B
#define A_OFF(buf,t) ((((buf)*3 + (t))) * TILE)
#define B_OFF(buf,t) ((6 + (buf)*3 + (t)) * TILE)
#define SM_BIAS (12 * TILE)          // 221184
#define SMEM_TOTAL (SM_BIAS + 512)   // 221696 B

// Pre-split router weights: 3 bf16 terms, packed bf16x2, row-major [e][k/2]
__device__ unsigned g_B[3][NEXP * HIDDEN / 2];

// ---------------- helpers ----------------
__device__ __forceinline__ void cp16(uint32_t dst, const void* src) {
    asm volatile("cp.async.cg.shared.global [%0], [%1], 16;" :: "r"(dst), "l"(src));
}
#define CP_COMMIT() asm volatile("cp.async.commit_group;" ::: "memory")
#define CP_WAIT0()  asm volatile("cp.async.wait_group 0;"  ::: "memory")

__device__ __forceinline__ void ldm4(uint32_t addr, uint32_t* r) {
    asm volatile("ldmatrix.sync.aligned.m8n8.x4.shared.b16 {%0,%1,%2,%3}, [%4];"
                 : "=r"(r[0]), "=r"(r[1]), "=r"(r[2]), "=r"(r[3]) : "r"(addr));
}
__device__ __forceinline__ void mma16816(float* c, const uint32_t* a,
                                         uint32_t b0, uint32_t b1) {
    asm volatile(
        "mma.sync.aligned.m16n8k16.row.col.f32.bf16.bf16.f32 "
        "{%0,%1,%2,%3}, {%4,%5,%6,%7}, {%8,%9}, {%0,%1,%2,%3};"
        : "+f"(c[0]), "+f"(c[1]), "+f"(c[2]), "+f"(c[3])
        : "r"(a[0]), "r"(a[1]), "r"(a[2]), "r"(a[3]), "r"(b0), "r"(b1));
}
// Split fp32 pair into 3 bf16x2 terms (a ~= t1+t2+t3, residual ~2^-27 rel)
__device__ __forceinline__ void split3(float f0, float f1,
                                       unsigned& p1, unsigned& p2, unsigned& p3) {
    asm("cvt.rn.bf16x2.f32 %0, %2, %1;" : "=r"(p1) : "f"(f0), "f"(f1));
    float h0 = __uint_as_float(p1 << 16);
    float h1 = __uint_as_float(p1 & 0xFFFF0000u);
    float r0 = f0 - h0, r1 = f1 - h1;
    asm("cvt.rn.bf16x2.f32 %0, %2, %1;" : "=r"(p2) : "f"(r0), "f"(r1));
    float m0 = __uint_as_float(p2 << 16);
    float m1 = __uint_as_float(p2 & 0xFFFF0000u);
    float s0 = r0 - m0, s1 = r1 - m1;
    asm("cvt.rn.bf16x2.f32 %0, %2, %1;" : "=r"(p3) : "f"(s0), "f"(s1));
}

// ---- once per launch: W -> 3 bf16 term planes ----
__global__ void presplit_w(const float* __restrict__ W) {
    int i = blockIdx.x * 256 + threadIdx.x;              // pair index
    float f0 = W[2 * i], f1 = W[2 * i + 1];
    unsigned p1, p2, p3;
    split3(f0, f1, p1, p2, p3);
    g_B[0][i] = p1; g_B[1][i] = p2; g_B[2][i] = p3;
}

// ---------------- fused GEMM(6-term bf16 HMMA) + sigmoid + top-8 ----------------
__global__ __launch_bounds__(THREADS, 1)
void router_mma_kernel(const float* __restrict__ h,
                       const float* __restrict__ bias,
                       float* __restrict__ outI,
                       float* __restrict__ outW)
{
    extern __shared__ char smem[];
    const uint32_t sb = (uint32_t)__cvta_generic_to_shared(smem);
    const int tid  = threadIdx.x;
    const int lane = tid & 31;
    const int w    = tid >> 5;
    const int mw   = w >> 1;          // warp m index 0..3 (32 tokens each)
    const int nw   = w & 1;           // warp n index 0..1 (64 experts each)
    const int tok0 = blockIdx.x * TM;

    float* bias_s = (float*)(smem + SM_BIAS);
    if (tid < NEXP) bias_s[tid] = bias[tid];

    float mst[2][8][4];               // master accumulator (RN adds on CUDA cores)
    #pragma unroll
    for (int mt = 0; mt < 2; mt++)
        #pragma unroll
        for (int nt = 0; nt < 8; nt++)
            #pragma unroll
            for (int c = 0; c < 4; c++) mst[mt][nt][c] = 0.f;

    float4 aReg[8];

    // ---- prologue: stage 0 ----
    #pragma unroll
    for (int j = 0; j < 12; j++) {
        const int c = tid + THREADS * j;
        const int t = c >> 10, row = (c >> 3) & 127, ch = c & 7;
        cp16(sb + B_OFF(0, t) + row * TSTRIDE + ch * 16,
             (const char*)g_B[t] + (size_t)row * (HIDDEN * 2) + ch * 16);
    }
    CP_COMMIT();
    #pragma unroll
    for (int j = 0; j < 8; j++) {
        const int c = tid + THREADS * j;
        aReg[j] = *(const float4*)(h + (size_t)(tok0 + (c >> 4)) * HIDDEN + (c & 15) * 4);
    }

    // product order smallest-first: (2,2),(1,3),(3,1),(1,2),(2,1),(1,1)
    const int ta[6] = {1, 0, 2, 0, 1, 0};
    const int tb[6] = {1, 2, 0, 1, 0, 0};

    for (int s = 0; s < STAGES; s++) {
        const int buf = s & 1;

        CP_WAIT0();                   // B(s) landed
        #pragma unroll
        for (int j = 0; j < 8; j++) { // split A(s) -> 3 bf16 tiles
            const int c = tid + THREADS * j;
            const int row = c >> 4, ch = c & 15;
            unsigned a1, a2, a3, b1, b2, b3;
            split3(aReg[j].x, aReg[j].y, a1, a2, a3);
            split3(aReg[j].z, aReg[j].w, b1, b2, b3);
            const int off = row * TSTRIDE + ch * 8;
            *(uint2*)(smem + A_OFF(buf, 0) + off) = make_uint2(a1, b1);
            *(uint2*)(smem + A_OFF(buf, 1) + off) = make_uint2(a2, b2);
            *(uint2*)(smem + A_OFF(buf, 2) + off) = make_uint2(a3, b3);
        }
        __syncthreads();

        if (s + 1 < STAGES) {         // prefetch stage s+1
            const int k0n = (s + 1) * KT;
            const int nb  = buf ^ 1;
            #pragma unroll
            for (int j = 0; j < 12; j++) {
                const int c = tid + THREADS * j;
                const int t = c >> 10, row = (c >> 3) & 127, ch = c & 7;
                cp16(sb + B_OFF(nb, t) + row * TSTRIDE + ch * 16,
                     (const char*)g_B[t] + (size_t)row * (HIDDEN * 2) + k0n * 2 + ch * 16);
            }
            #pragma unroll
            for (int j = 0; j < 8; j++) {
                const int c = tid + THREADS * j;
                aReg[j] = *(const float4*)(h + (size_t)(tok0 + (c >> 4)) * HIDDEN
                                             + k0n + (c & 15) * 4);
            }
        }
        CP_COMMIT();

        // ---- compute: fresh fragment accumulator per stage (bounds TC RZ drift) ----
        float frg[2][8][4];
        #pragma unroll
        for (int mt = 0; mt < 2; mt++)
            #pragma unroll
            for (int nt = 0; nt < 8; nt++)
                #pragma unroll
                for (int c = 0; c < 4; c++) frg[mt][nt][c] = 0.f;

        const uint32_t lrow = (uint32_t)(lane & 15) * TSTRIDE + (uint32_t)(lane >> 4) * 16;
        #pragma unroll
        for (int p = 0; p < 6; p++) {
            const uint32_t aBase = sb + A_OFF(buf, ta[p]) + mw * 32 * TSTRIDE + lrow;
            const uint32_t bBase = sb + B_OFF(buf, tb[p]) + nw * 64 * TSTRIDE + lrow;
            #pragma unroll
            for (int k16 = 0; k16 < 4; k16++) {
                const uint32_t kb = k16 * 32;
                uint32_t af[2][4];
                ldm4(aBase + kb, af[0]);
                ldm4(aBase + kb + 16 * TSTRIDE, af[1]);
                uint32_t bf[8][2];
                #pragma unroll
                for (int g = 0; g < 4; g++) {
                    uint32_t r[4];
                    ldm4(bBase + kb + g * 16 * TSTRIDE, r);
                    bf[2*g][0] = r[0]; bf[2*g][1] = r[2];
                    bf[2*g+1][0] = r[1]; bf[2*g+1][1] = r[3];
                }
                #pragma unroll
                for (int mt = 0; mt < 2; mt++)
                    #pragma unroll
                    for (int nt = 0; nt < 8; nt++)
                        mma16816(frg[mt][nt], af[mt], bf[nt][0], bf[nt][1]);
            }
        }
        // flush fragment -> master with round-to-nearest fp32 adds
        #pragma unroll
        for (int mt = 0; mt < 2; mt++)
            #pragma unroll
            for (int nt = 0; nt < 8; nt++)
                #pragma unroll
                for (int c = 0; c < 4; c++) mst[mt][nt][c] += frg[mt][nt][c];

        __syncthreads();
    }

    // ---- scores -> smem [128 tokens][132] ----
    float* sc = (float*)smem;
    #pragma unroll
    for (int mt = 0; mt < 2; mt++)
        #pragma unroll
        for (int nt = 0; nt < 8; nt++) {
            const int r = mw * 32 + mt * 16 + (lane >> 2);
            const int c = nw * 64 + nt * 8 + (lane & 3) * 2;
            sc[r * 132 + c]           = mst[mt][nt][0];
            sc[r * 132 + c + 1]       = mst[mt][nt][1];
            sc[(r + 8) * 132 + c]     = mst[mt][nt][2];
            sc[(r + 8) * 132 + c + 1] = mst[mt][nt][3];
        }
    __syncthreads();

    // ---- distributed top-8 (half-warp shuffle, tie -> lowest index) ----
    const unsigned FULL = 0xffffffffu;
    const int tx  = tid & 15;
    const int grp = tid >> 4;                         // 16 groups x 8 tokens
    for (int i = 0; i < 8; i++) {
        const int token = grp * 8 + i;
        float scv[8];
        #pragma unroll
        for (int j = 0; j < 8; j++) {
            float logit = sc[token * 132 + tx * 8 + j];
            float sig = 1.0f / (1.0f + expf(-logit));
            scv[j] = sig + bias_s[tx * 8 + j];        // corrected score
        }
        float rem[8];
        #pragma unroll
        for (int j = 0; j < 8; j++) rem[j] = scv[j];

        int   topi[TOPK]; float topraw[TOPK];
        float denom = 1e-20f;
        #pragma unroll
        for (int sel = 0; sel < TOPK; sel++) {
            float bv = -3.4e38f; int bi = NEXP;
            #pragma unroll
            for (int j = 0; j < 8; j++)
                if (rem[j] > bv) { bv = rem[j]; bi = tx * 8 + j; }
            #pragma unroll
            for (int off = 8; off; off >>= 1) {
                float ov = __shfl_xor_sync(FULL, bv, off, 16);
                int   oi = __shfl_xor_sync(FULL, bi, off, 16);
                if (ov > bv || (ov == bv && oi < bi)) { bv = ov; bi = oi; }
            }
            topi[sel]   = bi;
            float raw   = bv - bias_s[bi];            // raw sigmoid score
            topraw[sel] = raw;
            denom      += raw;
            const int lj = bi - tx * 8;
            if (lj >= 0 && lj < 8) rem[lj] = -3.4e38f;
        }
        if (tx == 0) {
            const size_t t = (size_t)(tok0 + token);
            const float inv = 1.0f / denom;
            #pragma unroll
            for (int sel = 0; sel < TOPK; sel++) {
                outI[t * TOPK + sel] = (float)topi[sel];
                outW[t * TOPK + sel] = topraw[sel] * inv;
            }
        }
    }
}

extern "C" void kernel_launch(void* const* d_in, const int* in_sizes, int n_in,
                              void* d_out, int out_size)
{
    const float* h    = (const float*)d_in[0];
    const float* W    = (const float*)d_in[1];
    const float* bias = (const float*)d_in[2];

    const int T = in_sizes[0] / HIDDEN;               // 16384

    float* out  = (float*)d_out;
    float* outI = out;
    float* outW = out + (size_t)T * TOPK;

    presplit_w<<<NEXP * HIDDEN / 512, 256>>>(W);

    static int smem_set = 0;
    if (!smem_set) {
        cudaFuncSetAttribute(router_mma_kernel,
                             cudaFuncAttributeMaxDynamicSharedMemorySize, SMEM_TOTAL);
        smem_set = 1;
    }
    router_mma_kernel<<<T / TM, THREADS, SMEM_TOTAL>>>(h, bias, outI, outW);
}